// round 6
// baseline (speedup 1.0000x reference)
#include <cuda_runtime.h>
#include <cuda_bf16.h>

// Problem constants
#define NB 32            // N
#define MODES 4
#define EYS 192          // EY_SIZE
#define EY_PLANE (EYS*EYS)          // 36864 floats
#define EY_PLANE4 (EY_PLANE/4)      // 9216 float4
#define EYROW4 (EYS/4)              // 48 float4 per Ey row
#define TOTAL 1184       // (N + 2*KNN + 1) * OUT_RES
#define NK (NB*NB)       // 1024

// Scratch: precomputed weights w[k][m] = U * neff*N0/(neff+N0), laid out [k*4+m]
__device__ float g_w[NK * MODES];

__global__ void compute_weights_kernel(const float* __restrict__ U,
                                       const float* __restrict__ neff) {
    int idx = blockIdx.x * blockDim.x + threadIdx.x;
    if (idx < NK * MODES) {
        float nf = neff[idx];
        float eta = nf * 1.5f / (nf + 1.5f);
        g_w[idx] = eta * U[idx];
    }
}

// One thread per (row r, 4-column group); warp = 128 consecutive columns.
// R2 inner loop (best measured) + pure 32-bit addressing (Ey < 2^31 bytes)
// + minBlocksPerSM=6 to force regs<=42 -> 48 warps/SM (75% occ).
// blockDim = (32, 8); grid = (10, 148). Default rasterization (locality-friendly).
__global__ __launch_bounds__(256, 6) void gather_en_kernel(
    const float* __restrict__ Ey,
    float* __restrict__ out)
{
    const int lane = threadIdx.x;
    const int r    = blockIdx.y * 8 + threadIdx.y;     // 0..1183, uniform per warp
    const int c    = blockIdx.x * 128 + lane * 4;      // 16B-aligned column
    const bool active = (c < TOTAL);

    // i-range uniform per warp
    int i_lo = (r - 160) >> 5; if (i_lo < 0) i_lo = 0;
    int i_hi = r >> 5;         if (i_hi > NB - 1) i_hi = NB - 1;

    // j-range per lane
    int j_lo = (c - 160) >> 5; if (j_lo < 0) j_lo = 0;
    int j_hi = c >> 5;         if (j_hi > NB - 1) j_hi = NB - 1;
    if (!active) { j_lo = 1; j_hi = 0; }               // tail lanes: no loads

    const float4* __restrict__ w4  = reinterpret_cast<const float4*>(g_w);
    const float4* __restrict__ Ey4 = reinterpret_cast<const float4*>(Ey);

    float4 acc = make_float4(0.f, 0.f, 0.f, 0.f);

    for (int i = i_lo; i <= i_hi; ++i) {
        const int x = r - (i << 5);                    // 0..191
        // 32-bit float4 offset of (k = i*32, m = 0, row x, col 0); max < 2^25
        const int base_i = (i << 5) * (MODES * EY_PLANE4) + x * EYROW4;
        for (int j = j_lo; j <= j_hi; ++j) {
            const int k  = (i << 5) + j;
            const int y4 = (c - (j << 5)) >> 2;        // 0..47 float4 within row
            const float4* p = Ey4 + (base_i + j * (MODES * EY_PLANE4) + y4);
            const float4 wv = __ldg(&w4[k]);           // uniform per warp, L1-hot

            const float4 e0 = __ldg(p);
            const float4 e1 = __ldg(p + EY_PLANE4);
            const float4 e2 = __ldg(p + 2 * EY_PLANE4);
            const float4 e3 = __ldg(p + 3 * EY_PLANE4);

            acc.x += wv.x * e0.x + wv.y * e1.x + wv.z * e2.x + wv.w * e3.x;
            acc.y += wv.x * e0.y + wv.y * e1.y + wv.z * e2.y + wv.w * e3.y;
            acc.z += wv.x * e0.z + wv.y * e1.z + wv.z * e2.z + wv.w * e3.z;
            acc.w += wv.x * e0.w + wv.y * e1.w + wv.z * e2.w + wv.w * e3.w;
        }
    }

    if (active) {
        *reinterpret_cast<float4*>(out + r * TOTAL + c) = acc;
    }
}

extern "C" void kernel_launch(void* const* d_in, const int* in_sizes, int n_in,
                              void* d_out, int out_size) {
    // Inputs (metadata order): hs (unused), U, neff, Ey
    const float* U    = (const float*)d_in[1];
    const float* neff = (const float*)d_in[2];
    const float* Ey   = (const float*)d_in[3];
    float* out = (float*)d_out;

    compute_weights_kernel<<<(NK * MODES + 255) / 256, 256>>>(U, neff);

    dim3 block(32, 8);
    dim3 grid((TOTAL + 127) / 128, TOTAL / 8);   // (10, 148)
    gather_en_kernel<<<grid, block>>>(Ey, out);
}

// round 7
// speedup vs baseline: 1.2205x; 1.2205x over previous
#include <cuda_runtime.h>
#include <cuda_bf16.h>

// Problem constants
#define NB 32            // N
#define MODES 4
#define EYS 192          // EY_SIZE
#define EY_PLANE (EYS*EYS)          // 36864 floats
#define EY_PLANE4 (EY_PLANE/4)      // 9216 float4
#define EYROW4 (EYS/4)              // 48 float4 per Ey row
#define TOTAL 1184       // (N + 2*KNN + 1) * OUT_RES
#define NK (NB*NB)       // 1024

// Scratch: precomputed weights w[k][m] = U * neff*N0/(neff+N0), laid out [k*4+m]
__device__ float g_w[NK * MODES];

__global__ void compute_weights_kernel(const float* __restrict__ U,
                                       const float* __restrict__ neff) {
    int idx = blockIdx.x * blockDim.x + threadIdx.x;
    if (idx < NK * MODES) {
        float nf = neff[idx];
        float eta = nf * 1.5f / (nf + 1.5f);
        g_w[idx] = eta * U[idx];
    }
}

// R2 kernel verbatim, with ONE change: blockIdx.y remapped center-out so the
// heavy (interior-row, 6 block-row) CTAs dispatch first and the light edge
// CTAs fill the scheduling tail. Columns (blockIdx.x) stay natural.
// blockDim = (32, 8); grid = (10, 148).
__global__ __launch_bounds__(256) void gather_en_kernel(
    const float* __restrict__ Ey,
    float* __restrict__ out)
{
    // Center-out row remap: launch order 73,74,72,75,...,0,147 (heavy first).
    int byl = blockIdx.y;
    const int by = (byl & 1) ? (74 + (byl >> 1)) : (73 - (byl >> 1));

    const int lane = threadIdx.x;
    const int r    = by * 8 + threadIdx.y;             // 0..1183, uniform per warp
    const int c    = blockIdx.x * 128 + lane * 4;      // 16B-aligned column
    const bool active = (c < TOTAL);

    // i-range uniform per warp
    int i_lo = (r - 160) >> 5; if (i_lo < 0) i_lo = 0;
    int i_hi = r >> 5;         if (i_hi > NB - 1) i_hi = NB - 1;

    // j-range per lane
    int j_lo = (c - 160) >> 5; if (j_lo < 0) j_lo = 0;
    int j_hi = c >> 5;         if (j_hi > NB - 1) j_hi = NB - 1;
    if (!active) { j_lo = 1; j_hi = 0; }               // tail lanes: no loads

    const float4* __restrict__ w4  = reinterpret_cast<const float4*>(g_w);
    const float4* __restrict__ Ey4 = reinterpret_cast<const float4*>(Ey);

    float4 acc = make_float4(0.f, 0.f, 0.f, 0.f);

    for (int i = i_lo; i <= i_hi; ++i) {
        const int x = r - (i << 5);                    // 0..191
        const long base_i = (long)(i << 5) * (MODES * EY_PLANE4) + (long)x * EYROW4;
        for (int j = j_lo; j <= j_hi; ++j) {
            const int k  = (i << 5) + j;
            const int y4 = (c - (j << 5)) >> 2;        // 0..47 float4 within row
            const float4* p = Ey4 + base_i + (long)j * (MODES * EY_PLANE4) + y4;
            const float4 wv = __ldg(&w4[k]);           // uniform per warp, L1-hot

            const float4 e0 = __ldg(p);
            const float4 e1 = __ldg(p + EY_PLANE4);
            const float4 e2 = __ldg(p + 2 * EY_PLANE4);
            const float4 e3 = __ldg(p + 3 * EY_PLANE4);

            acc.x += wv.x * e0.x + wv.y * e1.x + wv.z * e2.x + wv.w * e3.x;
            acc.y += wv.x * e0.y + wv.y * e1.y + wv.z * e2.y + wv.w * e3.y;
            acc.z += wv.x * e0.z + wv.y * e1.z + wv.z * e2.z + wv.w * e3.z;
            acc.w += wv.x * e0.w + wv.y * e1.w + wv.z * e2.w + wv.w * e3.w;
        }
    }

    if (active) {
        *reinterpret_cast<float4*>(out + (long)r * TOTAL + c) = acc;
    }
}

extern "C" void kernel_launch(void* const* d_in, const int* in_sizes, int n_in,
                              void* d_out, int out_size) {
    // Inputs (metadata order): hs (unused), U, neff, Ey
    const float* U    = (const float*)d_in[1];
    const float* neff = (const float*)d_in[2];
    const float* Ey   = (const float*)d_in[3];
    float* out = (float*)d_out;

    compute_weights_kernel<<<(NK * MODES + 255) / 256, 256>>>(U, neff);

    dim3 block(32, 8);
    dim3 grid((TOTAL + 127) / 128, TOTAL / 8);   // (10, 148)
    gather_en_kernel<<<grid, block>>>(Ey, out);
}